// round 1
// baseline (speedup 1.0000x reference)
#include <cuda_runtime.h>
#include <cuda_bf16.h>
#include <math.h>

// ---------------- problem constants ----------------
#define BB   4
#define HH   12
#define BH   48          // BB*HH
#define SS   4096
#define DD   64
#define LL   128
#define SEG  32          // SS / LL
#define SCALE 0.3535533905932738f   // 1/sqrt(sqrt(64))

// ---------------- device scratch (static, no allocation) ----------------
// big buffer reused for K3 logits [BH][L][S] and later K1 logits [BH][S][L]
__device__ float g_big[BH * LL * SS];          // 25.17M floats ~100.7MB
__device__ float g_Qlm[BH * LL * DD];
__device__ float g_Klm[BH * LL * DD];
__device__ float g_K2 [BH * LL * LL];
__device__ float g_Vm [BH * LL * LL];
__device__ float g_Vm2[BH * LL * LL];
__device__ float g_tKV[BH * LL * LL];
__device__ float g_tA [BH * LL * LL];
__device__ float g_tB [BH * LL * LL];
__device__ float g_M3 [BH * LL * DD];
__device__ float g_T  [BH * LL * DD];
__device__ unsigned g_scal[2];                 // max rowsum, max colsum (float bits)

// ---------------- landmarks: Q_lm, K_lm = scale * mean over SEG rows ----------------
__global__ void landmarks_kernel(const float* __restrict__ Q,
                                 const float* __restrict__ K)
{
    int bh = blockIdx.y;
    int l  = blockIdx.x;
    int d  = threadIdx.x;                      // 0..63
    const float* Qb = Q + ((size_t)bh * SS + (size_t)l * SEG) * DD;
    const float* Kb = K + ((size_t)bh * SS + (size_t)l * SEG) * DD;
    float sq = 0.f, sk = 0.f;
    #pragma unroll 8
    for (int j = 0; j < SEG; j++) {
        sq += Qb[(size_t)j * DD + d];
        sk += Kb[(size_t)j * DD + d];
    }
    float f = SCALE / (float)SEG;
    g_Qlm[((size_t)bh * LL + l) * DD + d] = sq * f;
    g_Klm[((size_t)bh * LL + l) * DD + d] = sk * f;
}

// ---------------- generic batched SGEMM ----------------
// C[b] = alpha*I + beta * (A[b] @ opB(B[b]))
// A: [M][K] row-major.  B: transB ? [N][K] : [K][N].  C: [M][N].
// M,N multiples of 64, K multiple of 16. 64x64 tile, 16x16 threads, 4x4/thread.
__global__ void mm_kernel(const float* __restrict__ A,
                          const float* __restrict__ B,
                          float* __restrict__ C,
                          int M, int N, int K,
                          long long sA, long long sB, long long sC,
                          int transB, float alpha, float beta)
{
    __shared__ float As[64][17];
    __shared__ float Bs[16][65];

    int b    = blockIdx.z;
    const float* Ab = A + (long long)b * sA;
    const float* Bb = B + (long long)b * sB;
    float*       Cb = C + (long long)b * sC;

    int row0 = blockIdx.y * 64;
    int col0 = blockIdx.x * 64;
    int tx = threadIdx.x, ty = threadIdx.y;
    int tid = ty * 16 + tx;

    float acc[4][4];
    #pragma unroll
    for (int r = 0; r < 4; r++)
        #pragma unroll
        for (int c = 0; c < 4; c++) acc[r][c] = 0.f;

    for (int k0 = 0; k0 < K; k0 += 16) {
        // load A tile 64x16
        #pragma unroll
        for (int t = 0; t < 4; t++) {
            int idx = tid + t * 256;
            int r = idx >> 4, kk = idx & 15;
            As[r][kk] = Ab[(long long)(row0 + r) * K + (k0 + kk)];
        }
        // load B tile 16x64
        if (transB) {
            #pragma unroll
            for (int t = 0; t < 4; t++) {
                int idx = tid + t * 256;
                int c = idx >> 4, kk = idx & 15;
                Bs[kk][c] = Bb[(long long)(col0 + c) * K + (k0 + kk)];
            }
        } else {
            #pragma unroll
            for (int t = 0; t < 4; t++) {
                int idx = tid + t * 256;
                int kk = idx >> 6, c = idx & 63;
                Bs[kk][c] = Bb[(long long)(k0 + kk) * N + (col0 + c)];
            }
        }
        __syncthreads();

        #pragma unroll
        for (int kk = 0; kk < 16; kk++) {
            float av[4], bv[4];
            #pragma unroll
            for (int r = 0; r < 4; r++) av[r] = As[ty + 16 * r][kk];
            #pragma unroll
            for (int c = 0; c < 4; c++) bv[c] = Bs[kk][tx + 16 * c];
            #pragma unroll
            for (int r = 0; r < 4; r++)
                #pragma unroll
                for (int c = 0; c < 4; c++)
                    acc[r][c] += av[r] * bv[c];
        }
        __syncthreads();
    }

    #pragma unroll
    for (int r = 0; r < 4; r++) {
        int gr = row0 + ty + 16 * r;
        #pragma unroll
        for (int c = 0; c < 4; c++) {
            int gc = col0 + tx + 16 * c;
            float v = beta * acc[r][c];
            if (gr == gc) v += alpha;
            Cb[(long long)gr * N + gc] = v;
        }
    }
}

// ---------------- generic row softmax (in place) ----------------
// grid.x = number of rows, block = 128 threads
__global__ void softmax_rows_kernel(float* __restrict__ X, int N)
{
    long long row = blockIdx.x;
    float* x = X + row * (long long)N;
    __shared__ float red[128];
    int tid = threadIdx.x;

    float m = -1e30f;
    for (int j = tid; j < N; j += 128) m = fmaxf(m, x[j]);
    red[tid] = m; __syncthreads();
    for (int s = 64; s > 0; s >>= 1) {
        if (tid < s) red[tid] = fmaxf(red[tid], red[tid + s]);
        __syncthreads();
    }
    m = red[0];
    __syncthreads();

    float ssum = 0.f;
    for (int j = tid; j < N; j += 128) ssum += __expf(x[j] - m);
    red[tid] = ssum; __syncthreads();
    for (int s = 64; s > 0; s >>= 1) {
        if (tid < s) red[tid] += red[tid + s];
        __syncthreads();
    }
    float inv = 1.f / red[0];
    __syncthreads();

    for (int j = tid; j < N; j += 128) x[j] = __expf(x[j] - m) * inv;
}

// ---------------- init-scale reduction over K2 ----------------
__global__ void zero_scal_kernel()
{
    if (threadIdx.x == 0) { g_scal[0] = 0u; g_scal[1] = 0u; }
}

__global__ void reduce_scal_kernel()
{
    int bh = blockIdx.x;
    int j  = threadIdx.x;                      // 0..127
    const float* K2b = g_K2 + (size_t)bh * LL * LL;
    float rowsum = 0.f, colsum = 0.f;
    for (int k = 0; k < LL; k++) {
        rowsum += K2b[(size_t)j * LL + k];
        colsum += K2b[(size_t)k * LL + j];
    }
    atomicMax(&g_scal[0], __float_as_uint(rowsum));
    atomicMax(&g_scal[1], __float_as_uint(colsum));
}

// Vm = init_scale * K2^T
__global__ void init_vm_kernel()
{
    int bh = blockIdx.y;
    int i  = blockIdx.x;
    int j  = threadIdx.x;
    float s = 1.f / (__uint_as_float(g_scal[0]) * __uint_as_float(g_scal[1]));
    g_Vm[((size_t)bh * LL + i) * LL + j] =
        s * g_K2[((size_t)bh * LL + j) * LL + i];
}

// tA = 7I - tKV (elementwise)
__global__ void ew7_kernel()
{
    size_t idx = (size_t)blockIdx.x * blockDim.x + threadIdx.x;
    if (idx >= (size_t)BH * LL * LL) return;
    int c = (int)(idx % LL);
    int r = (int)((idx / LL) % LL);
    float v = -g_tKV[idx];
    if (r == c) v += 7.f;
    g_tA[idx] = v;
}

// ---------------- host launch ----------------
extern "C" void kernel_launch(void* const* d_in, const int* in_sizes, int n_in,
                              void* d_out, int out_size)
{
    const float* Q = (const float*)d_in[0];
    const float* K = (const float*)d_in[1];
    const float* V = (const float*)d_in[2];
    // d_in[3] = mask (all ones) -- unused
    float* out = (float*)d_out;

    // resolve scratch symbol addresses (host API, not captured, deterministic)
    float *pBig, *pQlm, *pKlm, *pK2, *pVm, *pVm2, *pKV, *pA, *pB2, *pM3, *pT;
    cudaGetSymbolAddress((void**)&pBig, g_big);
    cudaGetSymbolAddress((void**)&pQlm, g_Qlm);
    cudaGetSymbolAddress((void**)&pKlm, g_Klm);
    cudaGetSymbolAddress((void**)&pK2,  g_K2);
    cudaGetSymbolAddress((void**)&pVm,  g_Vm);
    cudaGetSymbolAddress((void**)&pVm2, g_Vm2);
    cudaGetSymbolAddress((void**)&pKV,  g_tKV);
    cudaGetSymbolAddress((void**)&pA,   g_tA);
    cudaGetSymbolAddress((void**)&pB2,  g_tB);
    cudaGetSymbolAddress((void**)&pM3,  g_M3);
    cudaGetSymbolAddress((void**)&pT,   g_T);

    const long long sQ   = (long long)SS * DD;   // 262144
    const long long sLM  = (long long)LL * DD;   // 8192
    const long long sK2  = (long long)LL * LL;   // 16384
    const long long sBIG = (long long)LL * SS;   // 524288

    dim3 t16(16, 16);

    // 1. landmarks
    landmarks_kernel<<<dim3(LL, BH), DD>>>(Q, K);

    // 2. K2 = softmax(Qlm @ Klm^T)   (scales already folded into landmarks)
    mm_kernel<<<dim3(2, 2, BH), t16>>>(pQlm, pKlm, pK2,
                                       LL, LL, DD, sLM, sLM, sK2,
                                       1, 0.f, 1.f);
    softmax_rows_kernel<<<BH * LL, 128>>>(pK2, LL);

    // 3. init_scale reductions
    zero_scal_kernel<<<1, 32>>>();
    reduce_scal_kernel<<<BH, LL>>>();

    // 4. Vm = init_scale * K2^T
    init_vm_kernel<<<dim3(LL, BH), LL>>>();

    // 5. Newton-Schulz x6
    float* Vc = pVm;
    float* Vn = pVm2;
    for (int it = 0; it < 6; it++) {
        // KV = K2 @ Vc
        mm_kernel<<<dim3(2, 2, BH), t16>>>(pK2, Vc, pKV,
                                           LL, LL, LL, sK2, sK2, sK2,
                                           0, 0.f, 1.f);
        // tA = 7I - KV
        ew7_kernel<<<(BH * LL * LL + 255) / 256, 256>>>();
        // tB = 15I - KV @ tA
        mm_kernel<<<dim3(2, 2, BH), t16>>>(pKV, pA, pB2,
                                           LL, LL, LL, sK2, sK2, sK2,
                                           0, 15.f, -1.f);
        // tA = 13I - KV @ tB
        mm_kernel<<<dim3(2, 2, BH), t16>>>(pKV, pB2, pA,
                                           LL, LL, LL, sK2, sK2, sK2,
                                           0, 13.f, -1.f);
        // Vn = 0.25 * Vc @ tA
        mm_kernel<<<dim3(2, 2, BH), t16>>>(Vc, pA, Vn,
                                           LL, LL, LL, sK2, sK2, sK2,
                                           0, 0.f, 0.25f);
        float* tmp = Vc; Vc = Vn; Vn = tmp;
    }
    // Vc now holds iterative_inv(K2)

    // 6. K3 = softmax(Qlm @ (K*scale)^T)  -> g_big  [BH][L][S]
    mm_kernel<<<dim3(SS / 64, 2, BH), t16>>>(pQlm, K, pBig,
                                             LL, SS, DD, sLM, sQ, sBIG,
                                             1, 0.f, SCALE);
    softmax_rows_kernel<<<BH * LL, 128>>>(pBig, SS);

    // 7. M3 = K3 @ V   [BH][L][D]
    mm_kernel<<<dim3(1, 2, BH), t16>>>(pBig, V, pM3,
                                       LL, DD, SS, sBIG, sQ, sLM,
                                       0, 0.f, 1.f);

    // 8. T = inv @ M3  [BH][L][D]
    mm_kernel<<<dim3(1, 2, BH), t16>>>(Vc, pM3, pT,
                                       LL, DD, LL, sK2, sLM, sLM,
                                       0, 0.f, 1.f);

    // 9. K1 = softmax((Q*scale) @ Klm^T)  -> g_big  [BH][S][L]
    mm_kernel<<<dim3(2, SS / 64, BH), t16>>>(Q, pKlm, pBig,
                                             SS, LL, DD, sQ, sLM, sBIG,
                                             1, 0.f, SCALE);
    softmax_rows_kernel<<<BH * SS, 128>>>(pBig, LL);

    // 10. out = K1 @ T
    mm_kernel<<<dim3(1, SS / 64, BH), t16>>>(pBig, pT, out,
                                             SS, DD, LL, sBIG, sLM, sQ,
                                             0, 0.f, 1.f);
}

// round 2
// speedup vs baseline: 1.0003x; 1.0003x over previous
#include <cuda_runtime.h>
#include <cuda_bf16.h>
#include <math.h>

// ---------------- problem constants ----------------
#define BB   4
#define HH   12
#define BH   48          // BB*HH
#define SS   4096
#define DD   64
#define LL   128
#define SEG  32          // SS / LL
#define SCALE 0.3535533905932738f   // 1/sqrt(sqrt(64))

// ---------------- device scratch (static, no allocation) ----------------
// big buffer reused for K3 logits [BH][L][S] and later K1 logits [BH][S][L]
__device__ float g_big[BH * LL * SS];          // 25.17M floats ~100.7MB
__device__ float g_Qlm[BH * LL * DD];
__device__ float g_Klm[BH * LL * DD];
__device__ float g_K2 [BH * LL * LL];
__device__ float g_Vm [BH * LL * LL];
__device__ float g_Vm2[BH * LL * LL];
__device__ float g_tKV[BH * LL * LL];
__device__ float g_tA [BH * LL * LL];
__device__ float g_tB [BH * LL * LL];
__device__ float g_M3 [BH * LL * DD];
__device__ float g_T  [BH * LL * DD];
__device__ unsigned g_scal[2];                 // max rowsum, max colsum (float bits)

// ---------------- landmarks: Q_lm, K_lm = scale * mean over SEG rows ----------------
__global__ void landmarks_kernel(const float* __restrict__ Q,
                                 const float* __restrict__ K)
{
    int bh = blockIdx.y;
    int l  = blockIdx.x;
    int d  = threadIdx.x;                      // 0..63
    const float* Qb = Q + ((size_t)bh * SS + (size_t)l * SEG) * DD;
    const float* Kb = K + ((size_t)bh * SS + (size_t)l * SEG) * DD;
    float sq = 0.f, sk = 0.f;
    #pragma unroll 8
    for (int j = 0; j < SEG; j++) {
        sq += Qb[(size_t)j * DD + d];
        sk += Kb[(size_t)j * DD + d];
    }
    float f = SCALE / (float)SEG;
    g_Qlm[((size_t)bh * LL + l) * DD + d] = sq * f;
    g_Klm[((size_t)bh * LL + l) * DD + d] = sk * f;
}

// ---------------- generic batched SGEMM ----------------
// C[b] = alpha*I + beta * (A[b] @ opB(B[b]))
// A: [M][K] row-major.  B: transB ? [N][K] : [K][N].  C: [M][N].
// M,N multiples of 64, K multiple of 16. 64x64 tile, 16x16 threads, 4x4/thread.
__global__ void mm_kernel(const float* __restrict__ A,
                          const float* __restrict__ B,
                          float* __restrict__ C,
                          int M, int N, int K,
                          long long sA, long long sB, long long sC,
                          int transB, float alpha, float beta)
{
    __shared__ float As[64][17];
    __shared__ float Bs[16][65];

    int b    = blockIdx.z;
    const float* Ab = A + (long long)b * sA;
    const float* Bb = B + (long long)b * sB;
    float*       Cb = C + (long long)b * sC;

    int row0 = blockIdx.y * 64;
    int col0 = blockIdx.x * 64;
    int tx = threadIdx.x, ty = threadIdx.y;
    int tid = ty * 16 + tx;

    float acc[4][4];
    #pragma unroll
    for (int r = 0; r < 4; r++)
        #pragma unroll
        for (int c = 0; c < 4; c++) acc[r][c] = 0.f;

    for (int k0 = 0; k0 < K; k0 += 16) {
        // load A tile 64x16
        #pragma unroll
        for (int t = 0; t < 4; t++) {
            int idx = tid + t * 256;
            int r = idx >> 4, kk = idx & 15;
            As[r][kk] = Ab[(long long)(row0 + r) * K + (k0 + kk)];
        }
        // load B tile 16x64
        if (transB) {
            #pragma unroll
            for (int t = 0; t < 4; t++) {
                int idx = tid + t * 256;
                int c = idx >> 4, kk = idx & 15;
                Bs[kk][c] = Bb[(long long)(col0 + c) * K + (k0 + kk)];
            }
        } else {
            #pragma unroll
            for (int t = 0; t < 4; t++) {
                int idx = tid + t * 256;
                int kk = idx >> 6, c = idx & 63;
                Bs[kk][c] = Bb[(long long)(k0 + kk) * N + (col0 + c)];
            }
        }
        __syncthreads();

        #pragma unroll
        for (int kk = 0; kk < 16; kk++) {
            float av[4], bv[4];
            #pragma unroll
            for (int r = 0; r < 4; r++) av[r] = As[ty + 16 * r][kk];
            #pragma unroll
            for (int c = 0; c < 4; c++) bv[c] = Bs[kk][tx + 16 * c];
            #pragma unroll
            for (int r = 0; r < 4; r++)
                #pragma unroll
                for (int c = 0; c < 4; c++)
                    acc[r][c] += av[r] * bv[c];
        }
        __syncthreads();
    }

    #pragma unroll
    for (int r = 0; r < 4; r++) {
        int gr = row0 + ty + 16 * r;
        #pragma unroll
        for (int c = 0; c < 4; c++) {
            int gc = col0 + tx + 16 * c;
            float v = beta * acc[r][c];
            if (gr == gc) v += alpha;
            Cb[(long long)gr * N + gc] = v;
        }
    }
}

// ---------------- generic row softmax (in place) ----------------
// grid.x = number of rows, block = 128 threads
__global__ void softmax_rows_kernel(float* __restrict__ X, int N)
{
    long long row = blockIdx.x;
    float* x = X + row * (long long)N;
    __shared__ float red[128];
    int tid = threadIdx.x;

    float m = -1e30f;
    for (int j = tid; j < N; j += 128) m = fmaxf(m, x[j]);
    red[tid] = m; __syncthreads();
    for (int s = 64; s > 0; s >>= 1) {
        if (tid < s) red[tid] = fmaxf(red[tid], red[tid + s]);
        __syncthreads();
    }
    m = red[0];
    __syncthreads();

    float ssum = 0.f;
    for (int j = tid; j < N; j += 128) ssum += __expf(x[j] - m);
    red[tid] = ssum; __syncthreads();
    for (int s = 64; s > 0; s >>= 1) {
        if (tid < s) red[tid] += red[tid + s];
        __syncthreads();
    }
    float inv = 1.f / red[0];
    __syncthreads();

    for (int j = tid; j < N; j += 128) x[j] = __expf(x[j] - m) * inv;
}

// ---------------- init-scale reduction over K2 ----------------
__global__ void zero_scal_kernel()
{
    if (threadIdx.x == 0) { g_scal[0] = 0u; g_scal[1] = 0u; }
}

__global__ void reduce_scal_kernel()
{
    int bh = blockIdx.x;
    int j  = threadIdx.x;                      // 0..127
    const float* K2b = g_K2 + (size_t)bh * LL * LL;
    float rowsum = 0.f, colsum = 0.f;
    for (int k = 0; k < LL; k++) {
        rowsum += K2b[(size_t)j * LL + k];
        colsum += K2b[(size_t)k * LL + j];
    }
    atomicMax(&g_scal[0], __float_as_uint(rowsum));
    atomicMax(&g_scal[1], __float_as_uint(colsum));
}

// Vm = init_scale * K2^T
__global__ void init_vm_kernel()
{
    int bh = blockIdx.y;
    int i  = blockIdx.x;
    int j  = threadIdx.x;
    float s = 1.f / (__uint_as_float(g_scal[0]) * __uint_as_float(g_scal[1]));
    g_Vm[((size_t)bh * LL + i) * LL + j] =
        s * g_K2[((size_t)bh * LL + j) * LL + i];
}

// tA = 7I - tKV (elementwise)
__global__ void ew7_kernel()
{
    size_t idx = (size_t)blockIdx.x * blockDim.x + threadIdx.x;
    if (idx >= (size_t)BH * LL * LL) return;
    int c = (int)(idx % LL);
    int r = (int)((idx / LL) % LL);
    float v = -g_tKV[idx];
    if (r == c) v += 7.f;
    g_tA[idx] = v;
}

// ---------------- host launch ----------------
extern "C" void kernel_launch(void* const* d_in, const int* in_sizes, int n_in,
                              void* d_out, int out_size)
{
    const float* Q = (const float*)d_in[0];
    const float* K = (const float*)d_in[1];
    const float* V = (const float*)d_in[2];
    // d_in[3] = mask (all ones) -- unused
    float* out = (float*)d_out;

    // resolve scratch symbol addresses (host API, not captured, deterministic)
    float *pBig, *pQlm, *pKlm, *pK2, *pVm, *pVm2, *pKV, *pA, *pB2, *pM3, *pT;
    cudaGetSymbolAddress((void**)&pBig, g_big);
    cudaGetSymbolAddress((void**)&pQlm, g_Qlm);
    cudaGetSymbolAddress((void**)&pKlm, g_Klm);
    cudaGetSymbolAddress((void**)&pK2,  g_K2);
    cudaGetSymbolAddress((void**)&pVm,  g_Vm);
    cudaGetSymbolAddress((void**)&pVm2, g_Vm2);
    cudaGetSymbolAddress((void**)&pKV,  g_tKV);
    cudaGetSymbolAddress((void**)&pA,   g_tA);
    cudaGetSymbolAddress((void**)&pB2,  g_tB);
    cudaGetSymbolAddress((void**)&pM3,  g_M3);
    cudaGetSymbolAddress((void**)&pT,   g_T);

    const long long sQ   = (long long)SS * DD;   // 262144
    const long long sLM  = (long long)LL * DD;   // 8192
    const long long sK2  = (long long)LL * LL;   // 16384
    const long long sBIG = (long long)LL * SS;   // 524288

    dim3 t16(16, 16);

    // 1. landmarks
    landmarks_kernel<<<dim3(LL, BH), DD>>>(Q, K);

    // 2. K2 = softmax(Qlm @ Klm^T)   (scales already folded into landmarks)
    mm_kernel<<<dim3(2, 2, BH), t16>>>(pQlm, pKlm, pK2,
                                       LL, LL, DD, sLM, sLM, sK2,
                                       1, 0.f, 1.f);
    softmax_rows_kernel<<<BH * LL, 128>>>(pK2, LL);

    // 3. init_scale reductions
    zero_scal_kernel<<<1, 32>>>();
    reduce_scal_kernel<<<BH, LL>>>();

    // 4. Vm = init_scale * K2^T
    init_vm_kernel<<<dim3(LL, BH), LL>>>();

    // 5. Newton-Schulz x6
    float* Vc = pVm;
    float* Vn = pVm2;
    for (int it = 0; it < 6; it++) {
        // KV = K2 @ Vc
        mm_kernel<<<dim3(2, 2, BH), t16>>>(pK2, Vc, pKV,
                                           LL, LL, LL, sK2, sK2, sK2,
                                           0, 0.f, 1.f);
        // tA = 7I - KV
        ew7_kernel<<<(BH * LL * LL + 255) / 256, 256>>>();
        // tB = 15I - KV @ tA
        mm_kernel<<<dim3(2, 2, BH), t16>>>(pKV, pA, pB2,
                                           LL, LL, LL, sK2, sK2, sK2,
                                           0, 15.f, -1.f);
        // tA = 13I - KV @ tB
        mm_kernel<<<dim3(2, 2, BH), t16>>>(pKV, pB2, pA,
                                           LL, LL, LL, sK2, sK2, sK2,
                                           0, 13.f, -1.f);
        // Vn = 0.25 * Vc @ tA
        mm_kernel<<<dim3(2, 2, BH), t16>>>(Vc, pA, Vn,
                                           LL, LL, LL, sK2, sK2, sK2,
                                           0, 0.f, 0.25f);
        float* tmp = Vc; Vc = Vn; Vn = tmp;
    }
    // Vc now holds iterative_inv(K2)

    // 6. K3 = softmax(Qlm @ (K*scale)^T)  -> g_big  [BH][L][S]
    mm_kernel<<<dim3(SS / 64, 2, BH), t16>>>(pQlm, K, pBig,
                                             LL, SS, DD, sLM, sQ, sBIG,
                                             1, 0.f, SCALE);
    softmax_rows_kernel<<<BH * LL, 128>>>(pBig, SS);

    // 7. M3 = K3 @ V   [BH][L][D]
    mm_kernel<<<dim3(1, 2, BH), t16>>>(pBig, V, pM3,
                                       LL, DD, SS, sBIG, sQ, sLM,
                                       0, 0.f, 1.f);

    // 8. T = inv @ M3  [BH][L][D]
    mm_kernel<<<dim3(1, 2, BH), t16>>>(Vc, pM3, pT,
                                       LL, DD, LL, sK2, sLM, sLM,
                                       0, 0.f, 1.f);

    // 9. K1 = softmax((Q*scale) @ Klm^T)  -> g_big  [BH][S][L]
    mm_kernel<<<dim3(2, SS / 64, BH), t16>>>(Q, pKlm, pBig,
                                             SS, LL, DD, sQ, sLM, sBIG,
                                             1, 0.f, SCALE);
    softmax_rows_kernel<<<BH * SS, 128>>>(pBig, LL);

    // 10. out = K1 @ T
    mm_kernel<<<dim3(1, SS / 64, BH), t16>>>(pBig, pT, out,
                                             SS, DD, LL, sBIG, sLM, sQ,
                                             0, 0.f, 1.f);
}

// round 3
// speedup vs baseline: 1.7742x; 1.7737x over previous
#include <cuda_runtime.h>
#include <cuda_bf16.h>
#include <math.h>

// ---------------- problem constants ----------------
#define BB   4
#define HH   12
#define BH   48
#define SS   4096
#define DD   64
#define LL   128
#define SEG  32
#define NSPLIT 8
#define SCHUNK (SS / NSPLIT)     // 512
#define SCALE 0.3535533905932738f   // 1/sqrt(sqrt(64))

// ---------------- device scratch ----------------
__device__ float g_Qlm[BH * LL * DD];
__device__ float g_Klm[BH * LL * DD];
__device__ float g_K2 [BH * LL * LL];
__device__ float g_Vm [BH * LL * LL];
__device__ float g_Vm2[BH * LL * LL];
__device__ float g_tKV[BH * LL * LL];
__device__ float g_tA [BH * LL * LL];
__device__ float g_tB [BH * LL * LL];
__device__ float g_M3 [BH * LL * DD];
__device__ float g_T  [BH * LL * DD];
__device__ float g_pacc[(size_t)BH * NSPLIT * LL * DD];   // 12.6 MB
__device__ float g_pm  [BH * NSPLIT * LL];
__device__ float g_pl  [BH * NSPLIT * LL];
__device__ unsigned g_scal[2];

// ---------------- landmarks ----------------
__global__ void landmarks_kernel(const float* __restrict__ Q,
                                 const float* __restrict__ K)
{
    int bh = blockIdx.y;
    int l  = blockIdx.x;
    int d  = threadIdx.x;
    const float* Qb = Q + ((size_t)bh * SS + (size_t)l * SEG) * DD;
    const float* Kb = K + ((size_t)bh * SS + (size_t)l * SEG) * DD;
    float sq = 0.f, sk = 0.f;
    #pragma unroll 8
    for (int j = 0; j < SEG; j++) {
        sq += Qb[(size_t)j * DD + d];
        sk += Kb[(size_t)j * DD + d];
    }
    float f = SCALE / (float)SEG;
    g_Qlm[((size_t)bh * LL + l) * DD + d] = sq * f;
    g_Klm[((size_t)bh * LL + l) * DD + d] = sk * f;
}

// ---------------- generic batched SGEMM ----------------
// C[b] = alpha*I + beta * (A[b] @ opB(B[b]))
__global__ void mm_kernel(const float* __restrict__ A,
                          const float* __restrict__ B,
                          float* __restrict__ C,
                          int M, int N, int K,
                          long long sA, long long sB, long long sC,
                          int transB, float alpha, float beta)
{
    __shared__ float As[64][17];
    __shared__ float Bs[16][65];

    int b = blockIdx.z;
    const float* Ab = A + (long long)b * sA;
    const float* Bb = B + (long long)b * sB;
    float*       Cb = C + (long long)b * sC;

    int row0 = blockIdx.y * 64;
    int col0 = blockIdx.x * 64;
    int tx = threadIdx.x, ty = threadIdx.y;
    int tid = ty * 16 + tx;

    float acc[4][4];
    #pragma unroll
    for (int r = 0; r < 4; r++)
        #pragma unroll
        for (int c = 0; c < 4; c++) acc[r][c] = 0.f;

    for (int k0 = 0; k0 < K; k0 += 16) {
        #pragma unroll
        for (int t = 0; t < 4; t++) {
            int idx = tid + t * 256;
            int r = idx >> 4, kk = idx & 15;
            As[r][kk] = Ab[(long long)(row0 + r) * K + (k0 + kk)];
        }
        if (transB) {
            #pragma unroll
            for (int t = 0; t < 4; t++) {
                int idx = tid + t * 256;
                int c = idx >> 4, kk = idx & 15;
                Bs[kk][c] = Bb[(long long)(col0 + c) * K + (k0 + kk)];
            }
        } else {
            #pragma unroll
            for (int t = 0; t < 4; t++) {
                int idx = tid + t * 256;
                int kk = idx >> 6, c = idx & 63;
                Bs[kk][c] = Bb[(long long)(k0 + kk) * N + (col0 + c)];
            }
        }
        __syncthreads();

        #pragma unroll
        for (int kk = 0; kk < 16; kk++) {
            float av[4], bv[4];
            #pragma unroll
            for (int r = 0; r < 4; r++) av[r] = As[ty + 16 * r][kk];
            #pragma unroll
            for (int c = 0; c < 4; c++) bv[c] = Bs[kk][tx + 16 * c];
            #pragma unroll
            for (int r = 0; r < 4; r++)
                #pragma unroll
                for (int c = 0; c < 4; c++)
                    acc[r][c] += av[r] * bv[c];
        }
        __syncthreads();
    }

    #pragma unroll
    for (int r = 0; r < 4; r++) {
        int gr = row0 + ty + 16 * r;
        #pragma unroll
        for (int c = 0; c < 4; c++) {
            int gc = col0 + tx + 16 * c;
            float v = beta * acc[r][c];
            if (gr == gc) v += alpha;
            Cb[(long long)gr * N + gc] = v;
        }
    }
}

// ---------------- dual-output 128x128x128 GEMM for NS: KV = A@B, C2 = 7I - KV
__global__ void mm_kv_kernel(const float* __restrict__ A,
                             const float* __restrict__ B,
                             float* __restrict__ C,
                             float* __restrict__ C2)
{
    __shared__ float As[64][17];
    __shared__ float Bs[16][65];
    const int K = 128, N = 128;

    int b = blockIdx.z;
    const float* Ab = A + (long long)b * (LL * LL);
    const float* Bb = B + (long long)b * (LL * LL);
    float*       Cb = C + (long long)b * (LL * LL);
    float*       C2b = C2 + (long long)b * (LL * LL);

    int row0 = blockIdx.y * 64;
    int col0 = blockIdx.x * 64;
    int tx = threadIdx.x, ty = threadIdx.y;
    int tid = ty * 16 + tx;

    float acc[4][4];
    #pragma unroll
    for (int r = 0; r < 4; r++)
        #pragma unroll
        for (int c = 0; c < 4; c++) acc[r][c] = 0.f;

    for (int k0 = 0; k0 < K; k0 += 16) {
        #pragma unroll
        for (int t = 0; t < 4; t++) {
            int idx = tid + t * 256;
            int r = idx >> 4, kk = idx & 15;
            As[r][kk] = Ab[(long long)(row0 + r) * K + (k0 + kk)];
        }
        #pragma unroll
        for (int t = 0; t < 4; t++) {
            int idx = tid + t * 256;
            int kk = idx >> 6, c = idx & 63;
            Bs[kk][c] = Bb[(long long)(k0 + kk) * N + (col0 + c)];
        }
        __syncthreads();
        #pragma unroll
        for (int kk = 0; kk < 16; kk++) {
            float av[4], bv[4];
            #pragma unroll
            for (int r = 0; r < 4; r++) av[r] = As[ty + 16 * r][kk];
            #pragma unroll
            for (int c = 0; c < 4; c++) bv[c] = Bs[kk][tx + 16 * c];
            #pragma unroll
            for (int r = 0; r < 4; r++)
                #pragma unroll
                for (int c = 0; c < 4; c++)
                    acc[r][c] += av[r] * bv[c];
        }
        __syncthreads();
    }

    #pragma unroll
    for (int r = 0; r < 4; r++) {
        int gr = row0 + ty + 16 * r;
        #pragma unroll
        for (int c = 0; c < 4; c++) {
            int gc = col0 + tx + 16 * c;
            float v = acc[r][c];
            Cb[(long long)gr * N + gc] = v;
            float v2 = -v;
            if (gr == gc) v2 += 7.f;
            C2b[(long long)gr * N + gc] = v2;
        }
    }
}

// ---------------- row softmax (for K2 only) ----------------
__global__ void softmax_rows_kernel(float* __restrict__ X, int N)
{
    long long row = blockIdx.x;
    float* x = X + row * (long long)N;
    __shared__ float red[128];
    int tid = threadIdx.x;

    float m = -1e30f;
    for (int j = tid; j < N; j += 128) m = fmaxf(m, x[j]);
    red[tid] = m; __syncthreads();
    for (int s = 64; s > 0; s >>= 1) {
        if (tid < s) red[tid] = fmaxf(red[tid], red[tid + s]);
        __syncthreads();
    }
    m = red[0];
    __syncthreads();

    float ssum = 0.f;
    for (int j = tid; j < N; j += 128) ssum += __expf(x[j] - m);
    red[tid] = ssum; __syncthreads();
    for (int s = 64; s > 0; s >>= 1) {
        if (tid < s) red[tid] += red[tid + s];
        __syncthreads();
    }
    float inv = 1.f / red[0];
    __syncthreads();

    for (int j = tid; j < N; j += 128) x[j] = __expf(x[j] - m) * inv;
}

// ---------------- init-scale reduction ----------------
__global__ void zero_scal_kernel()
{
    if (threadIdx.x == 0) { g_scal[0] = 0u; g_scal[1] = 0u; }
}

__global__ void reduce_scal_kernel()
{
    int bh = blockIdx.x;
    int j  = threadIdx.x;
    const float* K2b = g_K2 + (size_t)bh * LL * LL;
    float rowsum = 0.f, colsum = 0.f;
    for (int k = 0; k < LL; k++) {
        rowsum += K2b[(size_t)j * LL + k];
        colsum += K2b[(size_t)k * LL + j];
    }
    atomicMax(&g_scal[0], __float_as_uint(rowsum));
    atomicMax(&g_scal[1], __float_as_uint(colsum));
}

__global__ void init_vm_kernel()
{
    int bh = blockIdx.y;
    int i  = blockIdx.x;
    int j  = threadIdx.x;
    float s = 1.f / (__uint_as_float(g_scal[0]) * __uint_as_float(g_scal[1]));
    g_Vm[((size_t)bh * LL + i) * LL + j] =
        s * g_K2[((size_t)bh * LL + j) * LL + i];
}

// ---------------- F1: fused softmax(Qlm @ K^T) @ V, split-KV flash ----------------
// grid (NSPLIT, BH), block (16,16), dyn smem 99840 B
__global__ void f1_kernel(const float* __restrict__ K, const float* __restrict__ V)
{
    extern __shared__ float sm[];
    float* Qs = sm;                      // [128][65]
    float* Ks = sm + 128 * 65;           // [64][65]
    float* Vs = Ks + 64 * 65;            // [64][65]
    float* Ps = Vs + 64 * 65;            // [128][65]

    int split = blockIdx.x, bh = blockIdx.y;
    int tx = threadIdx.x, ty = threadIdx.y;
    int tid = ty * 16 + tx;

    for (int i = tid; i < 128 * 64; i += 256) {
        int r = i >> 6, d = i & 63;
        Qs[r * 65 + d] = g_Qlm[(size_t)bh * 128 * 64 + i];
    }

    float m[8], l[8], acc[8][4];
    #pragma unroll
    for (int i = 0; i < 8; i++) {
        m[i] = -1e30f; l[i] = 0.f;
        #pragma unroll
        for (int c = 0; c < 4; c++) acc[i][c] = 0.f;
    }

    const float* Kb = K + (size_t)bh * SS * DD;
    const float* Vb = V + (size_t)bh * SS * DD;
    int base0 = split * SCHUNK;

    for (int kc = 0; kc < SCHUNK / 64; kc++) {
        int base = base0 + kc * 64;
        __syncthreads();    // previous chunk's Ks/Vs/Ps reads done
        for (int i = tid; i < 64 * 64; i += 256) {
            int r = i >> 6, d = i & 63;
            Ks[r * 65 + d] = Kb[(size_t)(base + r) * DD + d];
            Vs[r * 65 + d] = Vb[(size_t)(base + r) * DD + d];
        }
        __syncthreads();

        // scores: 128 x 64  (rows ty+16i, cols tx+16c)
        float s[8][4];
        #pragma unroll
        for (int i = 0; i < 8; i++)
            #pragma unroll
            for (int c = 0; c < 4; c++) s[i][c] = 0.f;

        #pragma unroll 4
        for (int d = 0; d < 64; d++) {
            float bv[4];
            #pragma unroll
            for (int c = 0; c < 4; c++) bv[c] = Ks[(tx + 16 * c) * 65 + d];
            #pragma unroll
            for (int i = 0; i < 8; i++) {
                float a = Qs[(ty + 16 * i) * 65 + d];
                #pragma unroll
                for (int c = 0; c < 4; c++) s[i][c] += a * bv[c];
            }
        }

        // online softmax per row
        #pragma unroll
        for (int i = 0; i < 8; i++) {
            float cm = -1e30f;
            #pragma unroll
            for (int c = 0; c < 4; c++) {
                s[i][c] *= SCALE;
                cm = fmaxf(cm, s[i][c]);
            }
            #pragma unroll
            for (int o = 8; o > 0; o >>= 1)
                cm = fmaxf(cm, __shfl_xor_sync(0xffffffffu, cm, o, 16));
            float mn = fmaxf(m[i], cm);
            float fct = __expf(m[i] - mn);
            float p[4], cs = 0.f;
            #pragma unroll
            for (int c = 0; c < 4; c++) { p[c] = __expf(s[i][c] - mn); cs += p[c]; }
            #pragma unroll
            for (int o = 8; o > 0; o >>= 1)
                cs += __shfl_xor_sync(0xffffffffu, cs, o, 16);
            l[i] = l[i] * fct + cs;
            m[i] = mn;
            #pragma unroll
            for (int c = 0; c < 4; c++) acc[i][c] *= fct;
            #pragma unroll
            for (int c = 0; c < 4; c++)
                Ps[(ty + 16 * i) * 65 + tx + 16 * c] = p[c];
        }
        __syncthreads();

        // acc += P @ Vc
        #pragma unroll 4
        for (int kk = 0; kk < 64; kk++) {
            float bv[4];
            #pragma unroll
            for (int c = 0; c < 4; c++) bv[c] = Vs[kk * 65 + tx + 16 * c];
            #pragma unroll
            for (int i = 0; i < 8; i++) {
                float pv = Ps[(ty + 16 * i) * 65 + kk];
                #pragma unroll
                for (int c = 0; c < 4; c++) acc[i][c] += pv * bv[c];
            }
        }
    }

    size_t pb = ((size_t)bh * NSPLIT + split) * LL;
    #pragma unroll
    for (int i = 0; i < 8; i++) {
        int row = ty + 16 * i;
        if (tx == 0) { g_pm[pb + row] = m[i]; g_pl[pb + row] = l[i]; }
        #pragma unroll
        for (int c = 0; c < 4; c++)
            g_pacc[(pb + row) * DD + tx + 16 * c] = acc[i][c];
    }
}

// combine partials -> M3
__global__ void combine_kernel()
{
    int row = blockIdx.x, bh = blockIdx.y, d = threadIdx.x;
    size_t pb = (size_t)bh * NSPLIT;
    float M = -1e30f;
    #pragma unroll
    for (int s = 0; s < NSPLIT; s++)
        M = fmaxf(M, g_pm[(pb + s) * LL + row]);
    float L = 0.f, val = 0.f;
    #pragma unroll
    for (int s = 0; s < NSPLIT; s++) {
        float w = __expf(g_pm[(pb + s) * LL + row] - M);
        L   += g_pl[(pb + s) * LL + row] * w;
        val += g_pacc[((pb + s) * LL + row) * DD + d] * w;
    }
    g_M3[((size_t)bh * LL + row) * DD + d] = val / L;
}

// ---------------- F2: fused softmax(Qs @ Klm^T) @ T -> out ----------------
// grid (SS/64, BH), block (16,16), dyn smem 83200 B
__global__ void f2_kernel(const float* __restrict__ Q, float* __restrict__ out)
{
    extern __shared__ float sm[];
    float* Qs = sm;                  // [64][65]
    float* Ls = sm + 64 * 65;        // [128][65]  Klm, later T
    float* Ps = Ls + 128 * 65;       // [64][130]

    int rb = blockIdx.x, bh = blockIdx.y;
    int tx = threadIdx.x, ty = threadIdx.y;
    int tid = ty * 16 + tx;
    int row0 = rb * 64;

    const float* Qb = Q + (size_t)bh * SS * DD + (size_t)row0 * DD;
    for (int i = tid; i < 64 * 64; i += 256) {
        int r = i >> 6, d = i & 63;
        Qs[r * 65 + d] = SCALE * Qb[i];
    }
    for (int i = tid; i < 128 * 64; i += 256) {
        int r = i >> 6, d = i & 63;
        Ls[r * 65 + d] = g_Klm[(size_t)bh * 128 * 64 + i];
    }
    __syncthreads();

    // logits: 64 x 128 (rows ty+16i i<4, cols tx+16c c<8)
    float s[4][8];
    #pragma unroll
    for (int i = 0; i < 4; i++)
        #pragma unroll
        for (int c = 0; c < 8; c++) s[i][c] = 0.f;

    #pragma unroll 4
    for (int d = 0; d < 64; d++) {
        float a[4];
        #pragma unroll
        for (int i = 0; i < 4; i++) a[i] = Qs[(ty + 16 * i) * 65 + d];
        #pragma unroll
        for (int c = 0; c < 8; c++) {
            float b = Ls[(tx + 16 * c) * 65 + d];
            #pragma unroll
            for (int i = 0; i < 4; i++) s[i][c] += a[i] * b;
        }
    }

    float invl[4];
    #pragma unroll
    for (int i = 0; i < 4; i++) {
        float mx = -1e30f;
        #pragma unroll
        for (int c = 0; c < 8; c++) mx = fmaxf(mx, s[i][c]);
        #pragma unroll
        for (int o = 8; o > 0; o >>= 1)
            mx = fmaxf(mx, __shfl_xor_sync(0xffffffffu, mx, o, 16));
        float sum = 0.f;
        float p[8];
        #pragma unroll
        for (int c = 0; c < 8; c++) { p[c] = __expf(s[i][c] - mx); sum += p[c]; }
        #pragma unroll
        for (int o = 8; o > 0; o >>= 1)
            sum += __shfl_xor_sync(0xffffffffu, sum, o, 16);
        invl[i] = 1.f / sum;
        #pragma unroll
        for (int c = 0; c < 8; c++)
            Ps[(ty + 16 * i) * 130 + tx + 16 * c] = p[c];
    }
    __syncthreads();

    // overwrite Ls with T
    for (int i = tid; i < 128 * 64; i += 256) {
        int r = i >> 6, d = i & 63;
        Ls[r * 65 + d] = g_T[(size_t)bh * 128 * 64 + i];
    }
    __syncthreads();

    // out = P @ T  (64 x 64)
    float o[4][4];
    #pragma unroll
    for (int i = 0; i < 4; i++)
        #pragma unroll
        for (int c = 0; c < 4; c++) o[i][c] = 0.f;

    #pragma unroll 4
    for (int kk = 0; kk < 128; kk++) {
        float b[4];
        #pragma unroll
        for (int c = 0; c < 4; c++) b[c] = Ls[kk * 65 + tx + 16 * c];
        #pragma unroll
        for (int i = 0; i < 4; i++) {
            float pv = Ps[(ty + 16 * i) * 130 + kk];
            #pragma unroll
            for (int c = 0; c < 4; c++) o[i][c] += pv * b[c];
        }
    }

    float* ob = out + (size_t)bh * SS * DD + (size_t)row0 * DD;
    #pragma unroll
    for (int i = 0; i < 4; i++)
        #pragma unroll
        for (int c = 0; c < 4; c++)
            ob[(size_t)(ty + 16 * i) * DD + tx + 16 * c] = o[i][c] * invl[i];
}

// ---------------- host launch ----------------
extern "C" void kernel_launch(void* const* d_in, const int* in_sizes, int n_in,
                              void* d_out, int out_size)
{
    const float* Q = (const float*)d_in[0];
    const float* K = (const float*)d_in[1];
    const float* V = (const float*)d_in[2];
    float* out = (float*)d_out;

    float *pQlm, *pKlm, *pK2, *pVm, *pVm2, *pKV, *pA, *pB2, *pM3, *pT;
    cudaGetSymbolAddress((void**)&pQlm, g_Qlm);
    cudaGetSymbolAddress((void**)&pKlm, g_Klm);
    cudaGetSymbolAddress((void**)&pK2,  g_K2);
    cudaGetSymbolAddress((void**)&pVm,  g_Vm);
    cudaGetSymbolAddress((void**)&pVm2, g_Vm2);
    cudaGetSymbolAddress((void**)&pKV,  g_tKV);
    cudaGetSymbolAddress((void**)&pA,   g_tA);
    cudaGetSymbolAddress((void**)&pB2,  g_tB);
    cudaGetSymbolAddress((void**)&pM3,  g_M3);
    cudaGetSymbolAddress((void**)&pT,   g_T);

    cudaFuncSetAttribute(f1_kernel, cudaFuncAttributeMaxDynamicSharedMemorySize, 99840);
    cudaFuncSetAttribute(f2_kernel, cudaFuncAttributeMaxDynamicSharedMemorySize, 83200);

    const long long sLM = (long long)LL * DD;
    const long long sK2 = (long long)LL * LL;

    dim3 t16(16, 16);

    // 0: landmarks
    landmarks_kernel<<<dim3(LL, BH), DD>>>(Q, K);

    // 1-2: K2 = softmax(Qlm @ Klm^T)
    mm_kernel<<<dim3(2, 2, BH), t16>>>(pQlm, pKlm, pK2,
                                       LL, LL, DD, sLM, sLM, sK2,
                                       1, 0.f, 1.f);
    softmax_rows_kernel<<<BH * LL, 128>>>(pK2, LL);

    // 3-4: init scale
    zero_scal_kernel<<<1, 32>>>();
    reduce_scal_kernel<<<BH, LL>>>();

    // 5: F1 (placed here so ncu -s 5 -c 1 captures it)
    f1_kernel<<<dim3(NSPLIT, BH), t16, 99840>>>(K, V);

    // 6: Vm = init_scale * K2^T
    init_vm_kernel<<<dim3(LL, BH), LL>>>();

    // Newton-Schulz x6 (4 launches each)
    float* Vc = pVm;
    float* Vn = pVm2;
    for (int it = 0; it < 6; it++) {
        mm_kv_kernel<<<dim3(2, 2, BH), t16>>>(pK2, Vc, pKV, pA);  // KV, tA = 7I-KV
        mm_kernel<<<dim3(2, 2, BH), t16>>>(pKV, pA, pB2,
                                           LL, LL, LL, sK2, sK2, sK2,
                                           0, 15.f, -1.f);
        mm_kernel<<<dim3(2, 2, BH), t16>>>(pKV, pB2, pA,
                                           LL, LL, LL, sK2, sK2, sK2,
                                           0, 13.f, -1.f);
        mm_kernel<<<dim3(2, 2, BH), t16>>>(Vc, pA, Vn,
                                           LL, LL, LL, sK2, sK2, sK2,
                                           0, 0.f, 0.25f);
        float* tmp = Vc; Vc = Vn; Vn = tmp;
    }

    // combine split-KV partials -> M3
    combine_kernel<<<dim3(LL, BH), DD>>>();

    // T = inv @ M3
    mm_kernel<<<dim3(1, 2, BH), t16>>>(Vc, pM3, pT,
                                       LL, DD, LL, sK2, sLM, sLM,
                                       0, 0.f, 1.f);

    // F2: out = softmax(Qs @ Klm^T) @ T
    f2_kernel<<<dim3(SS / 64, BH), t16, 83200>>>(Q, out);
}

// round 5
// speedup vs baseline: 2.6233x; 1.4786x over previous
#include <cuda_runtime.h>
#include <cuda_bf16.h>
#include <math.h>
#include <stdint.h>

// ---------------- problem constants ----------------
#define BB   4
#define HH   12
#define BH   48
#define SS   4096
#define DD   64
#define LL   128
#define SEG  32
#define NSPLIT 32                 // one 128-key chunk per split
#define SCALE 0.3535533905932738f // 1/sqrt(sqrt(64))

// ---------------- device scratch ----------------
__device__ float g_Qlm[BH * LL * DD];
__device__ float g_Klm[BH * LL * DD];
__device__ float g_K2 [BH * LL * LL];
__device__ float g_Vm [BH * LL * LL];
__device__ float g_Vm2[BH * LL * LL];
__device__ float g_tKV[BH * LL * LL];
__device__ float g_tA [BH * LL * LL];
__device__ float g_tB [BH * LL * LL];
__device__ float g_M3 [BH * LL * DD];
__device__ float g_T  [BH * LL * DD];
__device__ float g_pacc[(size_t)BH * NSPLIT * LL * DD];
__device__ float g_pm  [BH * NSPLIT * LL];
__device__ float g_pl  [BH * NSPLIT * LL];
__device__ unsigned g_scal[2];

// ---------------- helpers ----------------
__device__ __forceinline__ float tf32r(float x) {
    uint32_t u;
    asm("cvt.rna.tf32.f32 %0, %1;" : "=r"(u) : "f"(x));
    return __uint_as_float(u);
}

// D += A(16x8,row) @ B(8x8,col)  tf32
__device__ __forceinline__ void mma8(float* d,
                                     uint32_t a0, uint32_t a1, uint32_t a2, uint32_t a3,
                                     uint32_t b0, uint32_t b1) {
    asm volatile(
        "mma.sync.aligned.m16n8k8.row.col.f32.tf32.tf32.f32 "
        "{%0,%1,%2,%3}, {%4,%5,%6,%7}, {%8,%9}, {%0,%1,%2,%3};"
        : "+f"(d[0]), "+f"(d[1]), "+f"(d[2]), "+f"(d[3])
        : "r"(a0), "r"(a1), "r"(a2), "r"(a3), "r"(b0), "r"(b1));
}

// smem layout (floats)
#define STR_AB  68
#define STR_P   132
#define STR_BT  132
#define OFF_A   0
#define OFF_B1  8704
#define OFF_BT  17408
#define OFF_P   0            // overlays A+B1 (16896 <= 17408)
#define SMEM_FLOATS (17408 + 64 * STR_BT)   // 25856
#define SMEM_BYTES  (SMEM_FLOATS * 4)       // 103424

// ---------------- landmarks (+ zero g_scal) ----------------
__global__ void landmarks_kernel(const float* __restrict__ Q,
                                 const float* __restrict__ K)
{
    if (blockIdx.x == 0 && blockIdx.y == 0 && threadIdx.x == 0) {
        g_scal[0] = 0u; g_scal[1] = 0u;
    }
    int bh = blockIdx.y;
    int l  = blockIdx.x;
    int d  = threadIdx.x;
    const float* Qb = Q + ((size_t)bh * SS + (size_t)l * SEG) * DD;
    const float* Kb = K + ((size_t)bh * SS + (size_t)l * SEG) * DD;
    float sq = 0.f, sk = 0.f;
    #pragma unroll 8
    for (int j = 0; j < SEG; j++) {
        sq += Qb[(size_t)j * DD + d];
        sk += Kb[(size_t)j * DD + d];
    }
    float f = SCALE / (float)SEG;
    g_Qlm[((size_t)bh * LL + l) * DD + d] = sq * f;
    g_Klm[((size_t)bh * LL + l) * DD + d] = sk * f;
}

// ---------------- generic batched SGEMM (NS + small mats) ----------------
__global__ void mm_kernel(const float* __restrict__ A,
                          const float* __restrict__ B,
                          float* __restrict__ C,
                          int M, int N, int K,
                          long long sA, long long sB, long long sC,
                          int transB, float alpha, float beta)
{
    __shared__ float As[64][17];
    __shared__ float Bs[16][65];

    int b = blockIdx.z;
    const float* Ab = A + (long long)b * sA;
    const float* Bb = B + (long long)b * sB;
    float*       Cb = C + (long long)b * sC;

    int row0 = blockIdx.y * 64;
    int col0 = blockIdx.x * 64;
    int tx = threadIdx.x, ty = threadIdx.y;
    int tid = ty * 16 + tx;

    float acc[4][4];
    #pragma unroll
    for (int r = 0; r < 4; r++)
        #pragma unroll
        for (int c = 0; c < 4; c++) acc[r][c] = 0.f;

    for (int k0 = 0; k0 < K; k0 += 16) {
        #pragma unroll
        for (int t = 0; t < 4; t++) {
            int idx = tid + t * 256;
            int r = idx >> 4, kk = idx & 15;
            As[r][kk] = Ab[(long long)(row0 + r) * K + (k0 + kk)];
        }
        if (transB) {
            #pragma unroll
            for (int t = 0; t < 4; t++) {
                int idx = tid + t * 256;
                int c = idx >> 4, kk = idx & 15;
                Bs[kk][c] = Bb[(long long)(col0 + c) * K + (k0 + kk)];
            }
        } else {
            #pragma unroll
            for (int t = 0; t < 4; t++) {
                int idx = tid + t * 256;
                int kk = idx >> 6, c = idx & 63;
                Bs[kk][c] = Bb[(long long)(k0 + kk) * N + (col0 + c)];
            }
        }
        __syncthreads();

        #pragma unroll
        for (int kk = 0; kk < 16; kk++) {
            float av[4], bv[4];
            #pragma unroll
            for (int r = 0; r < 4; r++) av[r] = As[ty + 16 * r][kk];
            #pragma unroll
            for (int c = 0; c < 4; c++) bv[c] = Bs[kk][tx + 16 * c];
            #pragma unroll
            for (int r = 0; r < 4; r++)
                #pragma unroll
                for (int c = 0; c < 4; c++)
                    acc[r][c] += av[r] * bv[c];
        }
        __syncthreads();
    }

    #pragma unroll
    for (int r = 0; r < 4; r++) {
        int gr = row0 + ty + 16 * r;
        #pragma unroll
        for (int c = 0; c < 4; c++) {
            int gc = col0 + tx + 16 * c;
            float v = beta * acc[r][c];
            if (gr == gc) v += alpha;
            Cb[(long long)gr * N + gc] = v;
        }
    }
}

// dual-output NS kernel: C = A@B, C2 = 7I - C
__global__ void mm_kv_kernel(const float* __restrict__ A,
                             const float* __restrict__ B,
                             float* __restrict__ C,
                             float* __restrict__ C2)
{
    __shared__ float As[64][17];
    __shared__ float Bs[16][65];
    const int K = 128, N = 128;

    int b = blockIdx.z;
    const float* Ab = A + (long long)b * (LL * LL);
    const float* Bb = B + (long long)b * (LL * LL);
    float*       Cb = C + (long long)b * (LL * LL);
    float*       C2b = C2 + (long long)b * (LL * LL);

    int row0 = blockIdx.y * 64;
    int col0 = blockIdx.x * 64;
    int tx = threadIdx.x, ty = threadIdx.y;
    int tid = ty * 16 + tx;

    float acc[4][4];
    #pragma unroll
    for (int r = 0; r < 4; r++)
        #pragma unroll
        for (int c = 0; c < 4; c++) acc[r][c] = 0.f;

    for (int k0 = 0; k0 < K; k0 += 16) {
        #pragma unroll
        for (int t = 0; t < 4; t++) {
            int idx = tid + t * 256;
            int r = idx >> 4, kk = idx & 15;
            As[r][kk] = Ab[(long long)(row0 + r) * K + (k0 + kk)];
        }
        #pragma unroll
        for (int t = 0; t < 4; t++) {
            int idx = tid + t * 256;
            int kk = idx >> 6, c = idx & 63;
            Bs[kk][c] = Bb[(long long)(k0 + kk) * N + (col0 + c)];
        }
        __syncthreads();
        #pragma unroll
        for (int kk = 0; kk < 16; kk++) {
            float av[4], bv[4];
            #pragma unroll
            for (int r = 0; r < 4; r++) av[r] = As[ty + 16 * r][kk];
            #pragma unroll
            for (int c = 0; c < 4; c++) bv[c] = Bs[kk][tx + 16 * c];
            #pragma unroll
            for (int r = 0; r < 4; r++)
                #pragma unroll
                for (int c = 0; c < 4; c++)
                    acc[r][c] += av[r] * bv[c];
        }
        __syncthreads();
    }

    #pragma unroll
    for (int r = 0; r < 4; r++) {
        int gr = row0 + ty + 16 * r;
        #pragma unroll
        for (int c = 0; c < 4; c++) {
            int gc = col0 + tx + 16 * c;
            float v = acc[r][c];
            Cb[(long long)gr * N + gc] = v;
            float v2 = -v;
            if (gr == gc) v2 += 7.f;
            C2b[(long long)gr * N + gc] = v2;
        }
    }
}

// ---------------- row softmax (K2 only) ----------------
__global__ void softmax_rows_kernel(float* __restrict__ X, int N)
{
    long long row = blockIdx.x;
    float* x = X + row * (long long)N;
    __shared__ float red[128];
    int tid = threadIdx.x;

    float m = -1e30f;
    for (int j = tid; j < N; j += 128) m = fmaxf(m, x[j]);
    red[tid] = m; __syncthreads();
    for (int s = 64; s > 0; s >>= 1) {
        if (tid < s) red[tid] = fmaxf(red[tid], red[tid + s]);
        __syncthreads();
    }
    m = red[0];
    __syncthreads();

    float ssum = 0.f;
    for (int j = tid; j < N; j += 128) ssum += __expf(x[j] - m);
    red[tid] = ssum; __syncthreads();
    for (int s = 64; s > 0; s >>= 1) {
        if (tid < s) red[tid] += red[tid + s];
        __syncthreads();
    }
    float inv = 1.f / red[0];
    __syncthreads();

    for (int j = tid; j < N; j += 128) x[j] = __expf(x[j] - m) * inv;
}

__global__ void reduce_scal_kernel()
{
    int bh = blockIdx.x;
    int j  = threadIdx.x;
    const float* K2b = g_K2 + (size_t)bh * LL * LL;
    float rowsum = 0.f, colsum = 0.f;
    for (int k = 0; k < LL; k++) {
        rowsum += K2b[(size_t)j * LL + k];
        colsum += K2b[(size_t)k * LL + j];
    }
    atomicMax(&g_scal[0], __float_as_uint(rowsum));
    atomicMax(&g_scal[1], __float_as_uint(colsum));
}

__global__ void init_vm_kernel()
{
    int bh = blockIdx.y;
    int i  = blockIdx.x;
    int j  = threadIdx.x;
    float s = 1.f / (__uint_as_float(g_scal[0]) * __uint_as_float(g_scal[1]));
    g_Vm[((size_t)bh * LL + i) * LL + j] =
        s * g_K2[((size_t)bh * LL + j) * LL + i];
}

// ---------------- fused tensor-core softmax-GEMM (mma.sync tf32) ----------------
// mode 0 (F1): per (chunk cb, bh): D1 = Qlm @ (SCALE*Kchunk)^T -> softmax stats,
//              D2 = P @ Vchunk, write unnormalized partials + m,l
// mode 1 (F2): per (rowblk cb, bh): D1 = (SCALE*Qtile) @ Klm^T -> softmax,
//              D2 = P @ T, write normalized output
__global__ void __launch_bounds__(256, 2)
fused_attn_kernel(const float* __restrict__ Q,
                  const float* __restrict__ Kp,
                  const float* __restrict__ Vp,
                  float* __restrict__ out, int mode)
{
    extern __shared__ float sm[];
    float* sA  = sm + OFF_A;     // [128][68]
    float* sB1 = sm + OFF_B1;    // [128][68]
    float* sBt = sm + OFF_BT;    // [64][132]  (n-major: [d][k])
    float* sP  = sm + OFF_P;     // [128][132] overlay on A+B1

    int tid = threadIdx.x;
    int wid = tid >> 5, lane = tid & 31;
    int g = lane >> 2, t = lane & 3;
    int cb = blockIdx.x, bh = blockIdx.y;
    int m0 = wid * 16;

    // ---- fill tiles (tf32-rounded) ----
    if (mode == 0) {
        const float* A  = g_Qlm + (size_t)bh * (LL * DD);
        const float* Kb = Kp + ((size_t)bh * SS + (size_t)cb * 128) * DD;
        const float* Vb = Vp + ((size_t)bh * SS + (size_t)cb * 128) * DD;
        for (int i = tid; i < 128 * 64; i += 256) {
            int r = i >> 6, c = i & 63;
            sA [r * STR_AB + c] = tf32r(A[i]);
            sB1[r * STR_AB + c] = tf32r(SCALE * Kb[i]);
            sBt[c * STR_BT + r] = tf32r(Vb[i]);
        }
    } else {
        const float* Qb  = Q + ((size_t)bh * SS + (size_t)cb * 128) * DD;
        const float* Klm = g_Klm + (size_t)bh * (LL * DD);
        const float* Tm  = g_T + (size_t)bh * (LL * DD);
        for (int i = tid; i < 128 * 64; i += 256) {
            int r = i >> 6, c = i & 63;
            sA [r * STR_AB + c] = tf32r(SCALE * Qb[i]);
            sB1[r * STR_AB + c] = tf32r(Klm[i]);
            sBt[c * STR_BT + r] = tf32r(Tm[i]);
        }
    }
    __syncthreads();

    // ---- stage 1: D1[16 rows][128 cols] per warp, K=64 ----
    float acc[16][4];
    #pragma unroll
    for (int nt = 0; nt < 16; nt++)
        #pragma unroll
        for (int j = 0; j < 4; j++) acc[nt][j] = 0.f;

    #pragma unroll
    for (int kt = 0; kt < 8; kt++) {
        int k0 = kt * 8;
        uint32_t a0 = __float_as_uint(sA[(m0 + g)     * STR_AB + k0 + t]);
        uint32_t a1 = __float_as_uint(sA[(m0 + g + 8) * STR_AB + k0 + t]);
        uint32_t a2 = __float_as_uint(sA[(m0 + g)     * STR_AB + k0 + t + 4]);
        uint32_t a3 = __float_as_uint(sA[(m0 + g + 8) * STR_AB + k0 + t + 4]);
        #pragma unroll
        for (int nt = 0; nt < 16; nt++) {
            int n0 = nt * 8;
            uint32_t b0 = __float_as_uint(sB1[(n0 + g) * STR_AB + k0 + t]);
            uint32_t b1 = __float_as_uint(sB1[(n0 + g) * STR_AB + k0 + t + 4]);
            mma8(acc[nt], a0, a1, a2, a3, b0, b1);
        }
    }

    // ---- softmax over 128 cols (row fully in warp; 4-lane t-group holds cols) ----
    float mx0 = -1e30f, mx1 = -1e30f;
    #pragma unroll
    for (int nt = 0; nt < 16; nt++) {
        mx0 = fmaxf(mx0, fmaxf(acc[nt][0], acc[nt][1]));
        mx1 = fmaxf(mx1, fmaxf(acc[nt][2], acc[nt][3]));
    }
    mx0 = fmaxf(mx0, __shfl_xor_sync(0xffffffffu, mx0, 1));
    mx0 = fmaxf(mx0, __shfl_xor_sync(0xffffffffu, mx0, 2));
    mx1 = fmaxf(mx1, __shfl_xor_sync(0xffffffffu, mx1, 1));
    mx1 = fmaxf(mx1, __shfl_xor_sync(0xffffffffu, mx1, 2));

    float s0 = 0.f, s1 = 0.f;
    #pragma unroll
    for (int nt = 0; nt < 16; nt++) {
        acc[nt][0] = __expf(acc[nt][0] - mx0); s0 += acc[nt][0];
        acc[nt][1] = __expf(acc[nt][1] - mx0); s0 += acc[nt][1];
        acc[nt][2] = __expf(acc[nt][2] - mx1); s1 += acc[nt][2];
        acc[nt][3] = __expf(acc[nt][3] - mx1); s1 += acc[nt][3];
    }
    s0 += __shfl_xor_sync(0xffffffffu, s0, 1);
    s0 += __shfl_xor_sync(0xffffffffu, s0, 2);
    s1 += __shfl_xor_sync(0xffffffffu, s1, 1);
    s1 += __shfl_xor_sync(0xffffffffu, s1, 2);

    __syncthreads();   // all warps done reading sA/sB1 before P overwrites them

    #pragma unroll
    for (int nt = 0; nt < 16; nt++) {
        int n0 = nt * 8;
        sP[(m0 + g)     * STR_P + n0 + 2 * t]     = tf32r(acc[nt][0]);
        sP[(m0 + g)     * STR_P + n0 + 2 * t + 1] = tf32r(acc[nt][1]);
        sP[(m0 + g + 8) * STR_P + n0 + 2 * t]     = tf32r(acc[nt][2]);
        sP[(m0 + g + 8) * STR_P + n0 + 2 * t + 1] = tf32r(acc[nt][3]);
    }
    __syncthreads();

    // ---- stage 2: D2[16 rows][64 cols] per warp, K=128 ----
    float o[8][4];
    #pragma unroll
    for (int nt = 0; nt < 8; nt++)
        #pragma unroll
        for (int j = 0; j < 4; j++) o[nt][j] = 0.f;

    #pragma unroll
    for (int kt = 0; kt < 16; kt++) {
        int k0 = kt * 8;
        uint32_t a0 = __float_as_uint(sP[(m0 + g)     * STR_P + k0 + t]);
        uint32_t a1 = __float_as_uint(sP[(m0 + g + 8) * STR_P + k0 + t]);
        uint32_t a2 = __float_as_uint(sP[(m0 + g)     * STR_P + k0 + t + 4]);
        uint32_t a3 = __float_as_uint(sP[(m0 + g + 8) * STR_P + k0 + t + 4]);
        #pragma unroll
        for (int nt = 0; nt < 8; nt++) {
            int n0 = nt * 8;
            uint32_t b0 = __float_as_uint(sBt[(n0 + g) * STR_BT + k0 + t]);
            uint32_t b1 = __float_as_uint(sBt[(n0 + g) * STR_BT + k0 + t + 4]);
            mma8(o[nt], a0, a1, a2, a3, b0, b1);
        }
    }

    // ---- epilogue ----
    int r0 = m0 + g, r1 = m0 + g + 8;
    if (mode == 0) {
        size_t base = ((size_t)bh * NSPLIT + cb) * LL;
        #pragma unroll
        for (int nt = 0; nt < 8; nt++) {
            int n0 = nt * 8;
            g_pacc[(base + r0) * DD + n0 + 2 * t]     = o[nt][0];
            g_pacc[(base + r0) * DD + n0 + 2 * t + 1] = o[nt][1];
            g_pacc[(base + r1) * DD + n0 + 2 * t]     = o[nt][2];
            g_pacc[(base + r1) * DD + n0 + 2 * t + 1] = o[nt][3];
        }
        if (t == 0) {
            g_pm[base + r0] = mx0; g_pl[base + r0] = s0;
            g_pm[base + r1] = mx1; g_pl[base + r1] = s1;
        }
    } else {
        float inv0 = 1.f / s0, inv1 = 1.f / s1;
        float* ob = out + ((size_t)bh * SS + (size_t)cb * 128) * DD;
        #pragma unroll
        for (int nt = 0; nt < 8; nt++) {
            int n0 = nt * 8;
            ob[(size_t)r0 * DD + n0 + 2 * t]     = o[nt][0] * inv0;
            ob[(size_t)r0 * DD + n0 + 2 * t + 1] = o[nt][1] * inv0;
            ob[(size_t)r1 * DD + n0 + 2 * t]     = o[nt][2] * inv1;
            ob[(size_t)r1 * DD + n0 + 2 * t + 1] = o[nt][3] * inv1;
        }
    }
}

// combine split partials -> M3
__global__ void combine_kernel()
{
    int row = blockIdx.x, bh = blockIdx.y, d = threadIdx.x;
    size_t pb = (size_t)bh * NSPLIT;
    float M = -1e30f;
    #pragma unroll 8
    for (int s = 0; s < NSPLIT; s++)
        M = fmaxf(M, g_pm[(pb + s) * LL + row]);
    float L = 0.f, val = 0.f;
    #pragma unroll 8
    for (int s = 0; s < NSPLIT; s++) {
        float w = __expf(g_pm[(pb + s) * LL + row] - M);
        L   += g_pl[(pb + s) * LL + row] * w;
        val += g_pacc[((pb + s) * LL + row) * DD + d] * w;
    }
    g_M3[((size_t)bh * LL + row) * DD + d] = val / L;
}

// ---------------- host launch ----------------
extern "C" void kernel_launch(void* const* d_in, const int* in_sizes, int n_in,
                              void* d_out, int out_size)
{
    const float* Q = (const float*)d_in[0];
    const float* K = (const float*)d_in[1];
    const float* V = (const float*)d_in[2];
    float* out = (float*)d_out;

    float *pQlm, *pKlm, *pK2, *pVm, *pVm2, *pKV, *pA, *pB2, *pM3, *pT;
    cudaGetSymbolAddress((void**)&pQlm, g_Qlm);
    cudaGetSymbolAddress((void**)&pKlm, g_Klm);
    cudaGetSymbolAddress((void**)&pK2,  g_K2);
    cudaGetSymbolAddress((void**)&pVm,  g_Vm);
    cudaGetSymbolAddress((void**)&pVm2, g_Vm2);
    cudaGetSymbolAddress((void**)&pKV,  g_tKV);
    cudaGetSymbolAddress((void**)&pA,   g_tA);
    cudaGetSymbolAddress((void**)&pB2,  g_tB);
    cudaGetSymbolAddress((void**)&pM3,  g_M3);
    cudaGetSymbolAddress((void**)&pT,   g_T);

    cudaFuncSetAttribute(fused_attn_kernel,
                         cudaFuncAttributeMaxDynamicSharedMemorySize, SMEM_BYTES);

    const long long sLM = (long long)LL * DD;
    const long long sK2 = (long long)LL * LL;
    dim3 t16(16, 16);

    // landmarks (+ zero g_scal)
    landmarks_kernel<<<dim3(LL, BH), DD>>>(Q, K);

    // K2 = softmax(Qlm @ Klm^T)
    mm_kernel<<<dim3(2, 2, BH), t16>>>(pQlm, pKlm, pK2,
                                       LL, LL, DD, sLM, sLM, sK2,
                                       1, 0.f, 1.f);
    softmax_rows_kernel<<<BH * LL, 128>>>(pK2, LL);
    reduce_scal_kernel<<<BH, LL>>>();

    // F1: split partials of softmax(Qlm @ Ks^T) @ V
    fused_attn_kernel<<<dim3(NSPLIT, BH), 256, SMEM_BYTES>>>(Q, K, V, out, 0);

    // Vm = init_scale * K2^T
    init_vm_kernel<<<dim3(LL, BH), LL>>>();

    // Newton-Schulz x6
    float* Vc = pVm;
    float* Vn = pVm2;
    for (int it = 0; it < 6; it++) {
        mm_kv_kernel<<<dim3(2, 2, BH), t16>>>(pK2, Vc, pKV, pA);
        mm_kernel<<<dim3(2, 2, BH), t16>>>(pKV, pA, pB2,
                                           LL, LL, LL, sK2, sK2, sK2,
                                           0, 15.f, -1.f);
        mm_kernel<<<dim3(2, 2, BH), t16>>>(pKV, pB2, pA,
                                           LL, LL, LL, sK2, sK2, sK2,
                                           0, 13.f, -1.f);
        mm_kernel<<<dim3(2, 2, BH), t16>>>(Vc, pA, Vn,
                                           LL, LL, LL, sK2, sK2, sK2,
                                           0, 0.f, 0.25f);
        float* tmp = Vc; Vc = Vn; Vn = tmp;
    }

    // combine -> M3; T = inv @ M3
    combine_kernel<<<dim3(LL, BH), DD>>>();
    mm_kernel<<<dim3(1, 2, BH), t16>>>(Vc, pM3, pT,
                                       LL, DD, LL, sK2, sLM, sLM,
                                       0, 0.f, 1.f);

    // F2: out = softmax(Qs @ Klm^T) @ T
    fused_attn_kernel<<<dim3(SS / 128, BH), 256, SMEM_BYTES>>>(Q, K, V, out, 1);
}